// round 5
// baseline (speedup 1.0000x reference)
#include <cuda_runtime.h>
#include <math.h>

typedef unsigned long long u64;

// ---------------- pretransposed weights (device scratch) ----------------
__device__ float g_WqT[16384];   // [c][j] = Wq[j][c] * 1/sqrt(32)
__device__ float g_WvT[16384];   // [c][j] = Wv[j][c]
__device__ float g_WoT[16384];   // [j2][oc] = Wo[oc][j2]
__device__ float g_Se1T[4096];   // [oc][i] = Wse1[i][oc]
__device__ float g_Se2T[4096];   // [i][oc] = Wse2[oc][i]
__device__ float g_bqs[128];     // bq * 1/sqrt(32)

#define SCALE 0.17677669529663687f

__global__ void k_pre(const float* __restrict__ Wq, const float* __restrict__ bq,
                      const float* __restrict__ Wv, const float* __restrict__ Wo,
                      const float* __restrict__ Wse1, const float* __restrict__ Wse2)
{
    int i = blockIdx.x * 256 + threadIdx.x;
    if (i < 16384) {
        int a = i >> 7, b = i & 127;          // i = a*128 + b
        g_WqT[i] = Wq[b*128 + a] * SCALE;     // WqT[c][j]
        g_WvT[i] = Wv[b*128 + a];
        g_WoT[i] = Wo[b*128 + a];             // WoT[j2][oc]
    }
    if (i < 4096) {
        int oc1 = i >> 5, i1 = i & 31;        // i = oc1*32 + i1
        g_Se1T[i] = Wse1[i1*128 + oc1];
        int i2 = i >> 7, oc2 = i & 127;       // i = i2*128 + oc2
        g_Se2T[i] = Wse2[oc2*32 + i2];
    }
    if (i < 128) g_bqs[i] = bq[i] * SCALE;
}

// ---------------- helpers ----------------
__device__ __forceinline__ u64 pk2(float lo, float hi) {
    u64 r; asm("mov.b64 %0, {%1, %2};" : "=l"(r) : "f"(lo), "f"(hi)); return r;
}
__device__ __forceinline__ void upk(u64 v, float& lo, float& hi) {
    asm("mov.b64 {%0, %1}, %2;" : "=f"(lo), "=f"(hi) : "l"(v));
}
__device__ __forceinline__ u64 fma2(u64 a, u64 b, u64 c) {
    u64 d; asm("fma.rn.f32x2 %0, %1, %2, %3;" : "=l"(d) : "l"(a), "l"(b), "l"(c)); return d;
}
__device__ __forceinline__ void cpa16(unsigned dst, const void* src) {
    asm volatile("cp.async.cg.shared.global [%0], [%1], 16;" :: "r"(dst), "l"(src));
}
__device__ __forceinline__ void cp_commit() { asm volatile("cp.async.commit_group;"); }
__device__ __forceinline__ void cp_waitall() { asm volatile("cp.async.wait_group 0;" ::: "memory"); }
__device__ __forceinline__ float sigm(float z) { return 1.0f / (1.0f + __expf(-z)); }

// ---------------- smem layout (floats) ----------------
#define W1   0        // 16384: WqT -> WvT -> [Se1T | Se2T | Wg]
#define W2   16384    // 16384: Wk (verbatim) -> WoT
#define CTX  32768    // 17408: qk[32][512] -> ctxT[512][34] ; o2T[128][34]@+0 ; oT[128][34]@+13056
#define OT   (CTX + 13056)
#define O2T  (CTX + 0)
#define XT   50176    // 4352: xT[128][34]
#define SS   54528    // 2560: scores [(row*20+n)*4 + h] -> T1[i][34]
#define GG   57088    // 32: gates
#define SMEM_FLOATS 57120   // 228480 bytes

__global__ void __launch_bounds__(512, 1) k_fused(
    const float* __restrict__ x,
    const float* __restrict__ nb,
    const float* __restrict__ Wk,
    const float* __restrict__ bv, const float* __restrict__ bo,
    const float* __restrict__ Wg, const float* __restrict__ bg,
    float* __restrict__ out)
{
    extern __shared__ float sm[];
    const int t = threadIdx.x;
    const int lane = t & 31;
    const int w = t >> 5;              // warp 0..15
    const long rowBase = (long)blockIdx.x * 32;
    unsigned sb = (unsigned)__cvta_generic_to_shared(sm);

    // ---------------- phase 0: cp.async WqT->W1, Wk->W2 ; build xT ----------------
    #pragma unroll
    for (int i = t; i < 4096; i += 512) cpa16(sb + W1*4 + i*16, g_WqT + i*4);
    #pragma unroll
    for (int i = t; i < 4096; i += 512) cpa16(sb + W2*4 + i*16, Wk + i*4);
    cp_commit();
    {
        const float4* xg = (const float4*)x + rowBase*32;
        #pragma unroll
        for (int it = 0; it < 2; it++) {
            int idx = t + 512*it;
            int r = idx >> 5, c4 = idx & 31;
            float4 v = xg[idx];
            sm[XT + (c4*4+0)*34 + r] = v.x;
            sm[XT + (c4*4+1)*34 + r] = v.y;
            sm[XT + (c4*4+2)*34 + r] = v.z;
            sm[XT + (c4*4+3)*34 + r] = v.w;
        }
    }
    cp_waitall();
    __syncthreads();

    // ---------------- stage A: q = s*(Wq x + bq), kept in registers ----------------
    const int jg = w & 3, rg = w >> 2;
    const int rb = rg * 8;
    u64 q2[4];
    {
        const int j = jg*32 + lane;
        float b = g_bqs[j];
        u64 bb = pk2(b, b);
        #pragma unroll
        for (int p = 0; p < 4; p++) q2[p] = bb;
        #pragma unroll 4
        for (int c = 0; c < 128; c++) {
            float wq = sm[W1 + c*128 + j];
            u64 wp = pk2(wq, wq);
            #pragma unroll
            for (int p = 0; p < 4; p++) {
                u64 xp = *(const u64*)&sm[XT + c*34 + rb + 2*p];
                q2[p] = fma2(wp, xp, q2[p]);
            }
        }
    }
    __syncwarp();

    // ---------------- stage B: qk = q^T Wk (head h = jg), q via shuffles ----------------
    {
        float qlo[4], qhi[4];
        #pragma unroll
        for (int p = 0; p < 4; p++) upk(q2[p], qlo[p], qhi[p]);
        u64 acc[4][4];
        #pragma unroll
        for (int k = 0; k < 4; k++)
            #pragma unroll
            for (int p = 0; p < 4; p++) acc[k][p] = 0ull;
        #pragma unroll 2
        for (int d = 0; d < 32; d++) {
            u64 qq[4];
            #pragma unroll
            for (int p = 0; p < 4; p++) {
                float a = __shfl_sync(0xffffffffu, qlo[p], d);
                float b = __shfl_sync(0xffffffffu, qhi[p], d);
                qq[p] = pk2(a, b);
            }
            const int jrow = W2 + (jg*32 + d)*128 + lane;
            #pragma unroll
            for (int k = 0; k < 4; k++) {
                float wk = sm[jrow + 32*k];
                u64 wp = pk2(wk, wk);
                #pragma unroll
                for (int p = 0; p < 4; p++) acc[k][p] = fma2(wp, qq[p], acc[k][p]);
            }
        }
        #pragma unroll
        for (int k = 0; k < 4; k++)
            #pragma unroll
            for (int p = 0; p < 4; p++) {
                float lo, hi; upk(acc[k][p], lo, hi);
                sm[CTX + (rb+2*p  )*512 + jg*128 + lane + 32*k] = lo;
                sm[CTX + (rb+2*p+1)*512 + jg*128 + lane + 32*k] = hi;
            }
    }
    __syncthreads();

    // prefetch WvT -> W1, WoT -> W2 (overlaps attention phase)
    #pragma unroll
    for (int i = t; i < 4096; i += 512) cpa16(sb + W1*4 + i*16, g_WvT + i*4);
    #pragma unroll
    for (int i = t; i < 4096; i += 512) cpa16(sb + W2*4 + i*16, g_WoT + i*4);
    cp_commit();

    // ---------------- stage C1: scores ----------------
    for (int idx = t; idx < 640; idx += 512) {
        const int row = idx / 20;
        const int n = idx - row*20;
        const float4* nbp = (const float4*)(nb + (((rowBase + row)*20 + n) << 7));
        float a0 = 0.f, a1 = 0.f, a2 = 0.f, a3 = 0.f;
        #pragma unroll 8
        for (int c4 = 0; c4 < 32; c4++) {
            float4 v = nbp[c4];
            float4 h0 = *(const float4*)&sm[CTX + row*512 +   0 + c4*4];
            float4 h1 = *(const float4*)&sm[CTX + row*512 + 128 + c4*4];
            float4 h2 = *(const float4*)&sm[CTX + row*512 + 256 + c4*4];
            float4 h3 = *(const float4*)&sm[CTX + row*512 + 384 + c4*4];
            a0 += h0.x*v.x + h0.y*v.y + h0.z*v.z + h0.w*v.w;
            a1 += h1.x*v.x + h1.y*v.y + h1.z*v.z + h1.w*v.w;
            a2 += h2.x*v.x + h2.y*v.y + h2.z*v.z + h2.w*v.w;
            a3 += h3.x*v.x + h3.y*v.y + h3.z*v.z + h3.w*v.w;
        }
        *(float4*)&sm[SS + idx*4] = make_float4(a0, a1, a2, a3);
    }
    __syncthreads();

    // ---------------- stage C2: softmax over n (128 threads) ----------------
    if (t < 128) {
        const int row = t >> 2, h = t & 3;
        const int base = SS + row*80 + h;
        float m = -1e30f;
        float s[20];
        #pragma unroll
        for (int n = 0; n < 20; n++) { s[n] = sm[base + n*4]; m = fmaxf(m, s[n]); }
        float tot = 0.f;
        #pragma unroll
        for (int n = 0; n < 20; n++) { s[n] = __expf(s[n] - m); tot += s[n]; }
        float inv = 1.0f / tot;
        #pragma unroll
        for (int n = 0; n < 20; n++) sm[base + n*4] = s[n] * inv;
    }
    __syncthreads();

    // ---------------- stage C3: ctxT[h*128+c][row] ----------------
    {
        const int cq = w & 3, rq = w >> 2;
        const int c = cq*32 + lane;
        u64 cacc[8][2];
        #pragma unroll
        for (int r = 0; r < 8; r++) { cacc[r][0] = 0ull; cacc[r][1] = 0ull; }
        #pragma unroll
        for (int r = 0; r < 8; r++) {
            const int row = rq*8 + r;
            const float* nbr = nb + ((rowBase + row)*20 << 7) + c;
            #pragma unroll 4
            for (int n = 0; n < 20; n++) {
                float v = __ldg(nbr + n*128);
                u64 vp = pk2(v, v);
                u64 a01 = *(const u64*)&sm[SS + row*80 + n*4];
                u64 a23 = *(const u64*)&sm[SS + row*80 + n*4 + 2];
                cacc[r][0] = fma2(a01, vp, cacc[r][0]);
                cacc[r][1] = fma2(a23, vp, cacc[r][1]);
            }
        }
        __syncthreads();   // qk fully consumed (C1) before ctxT overwrites region
        #pragma unroll
        for (int r = 0; r < 8; r++) {
            const int row = rq*8 + r;
            float v0, v1, v2, v3;
            upk(cacc[r][0], v0, v1);
            upk(cacc[r][1], v2, v3);
            sm[CTX + (0*128 + c)*34 + row] = v0;
            sm[CTX + (1*128 + c)*34 + row] = v1;
            sm[CTX + (2*128 + c)*34 + row] = v2;
            sm[CTX + (3*128 + c)*34 + row] = v3;
        }
    }
    cp_waitall();          // WvT / WoT landed
    __syncthreads();

    // ---------------- stage D: o = Wv ctx + bv ----------------
    u64 dacc[4];
    {
        const int h = jg;                     // reuse warp mapping (h, rg)
        const int j = h*32 + lane;
        float b = __ldg(&bv[j]);
        u64 bb = pk2(b, b);
        #pragma unroll
        for (int p = 0; p < 4; p++) dacc[p] = bb;
        #pragma unroll 2
        for (int c = 0; c < 128; c++) {
            float wv = sm[W1 + c*128 + j];
            u64 wp = pk2(wv, wv);
            const int base = CTX + (h*128 + c)*34 + rb;
            #pragma unroll
            for (int p = 0; p < 4; p++) {
                u64 cv = *(const u64*)&sm[base + 2*p];
                dacc[p] = fma2(wp, cv, dacc[p]);
            }
        }
    }
    __syncthreads();       // all ctxT reads done before oT overwrites tail of region
    {
        const int j2 = lane*4 + jg;           // permuted index d*4+h
        #pragma unroll
        for (int p = 0; p < 4; p++)
            *(u64*)&sm[OT + j2*34 + rb + 2*p] = dacc[p];
    }
    // prefetch SE weights -> W1 (Wv dead)
    #pragma unroll
    for (int i = t; i < 1024; i += 512) cpa16(sb + W1*4 + i*16, g_Se1T + i*4);
    #pragma unroll
    for (int i = t; i < 1024; i += 512) cpa16(sb + (W1+4096)*4 + i*16, g_Se2T + i*4);
    if (t < 64) cpa16(sb + (W1+8192)*4 + t*16, Wg + t*4);
    cp_commit();
    __syncthreads();       // oT visible

    // ---------------- stage E: o2 = WoT . o + bo ----------------
    {
        const int oc = jg*32 + lane;          // (og, rg) mapping
        float b = __ldg(&bo[oc]);
        u64 bb = pk2(b, b);
        u64 eacc[4];
        #pragma unroll
        for (int p = 0; p < 4; p++) eacc[p] = bb;
        #pragma unroll 2
        for (int j2 = 0; j2 < 128; j2++) {
            float wo = sm[W2 + j2*128 + oc];
            u64 wp = pk2(wo, wo);
            const int base = OT + j2*34 + rb;
            #pragma unroll
            for (int p = 0; p < 4; p++) {
                u64 ov = *(const u64*)&sm[base + 2*p];
                eacc[p] = fma2(wp, ov, eacc[p]);
            }
        }
        #pragma unroll
        for (int p = 0; p < 4; p++)           // o2T region disjoint from oT
            *(u64*)&sm[O2T + oc*34 + rb + 2*p] = eacc[p];
    }
    cp_waitall();          // SE weights landed
    __syncthreads();

    // ---------------- stage F: T1 = relu(Se1 . o2), row-pair per warp ----------------
    {
        u64 facc = 0ull;
        #pragma unroll 4
        for (int oc = 0; oc < 128; oc++) {
            float wv = sm[W1 + oc*32 + lane];
            u64 wp = pk2(wv, wv);
            u64 ov = *(const u64*)&sm[O2T + oc*34 + 2*w];
            facc = fma2(wp, ov, facc);
        }
        float lo, hi; upk(facc, lo, hi);
        lo = fmaxf(lo, 0.0f); hi = fmaxf(hi, 0.0f);
        *(u64*)&sm[SS + lane*34 + 2*w] = pk2(lo, hi);   // T1[i][rowpos]
    }
    __syncthreads();

    // ---------------- stage G: o2 *= sigmoid(Se2 . T1) ----------------
    {
        const int oc = jg*32 + lane;
        u64 gacc[4];
        #pragma unroll
        for (int p = 0; p < 4; p++) gacc[p] = 0ull;
        #pragma unroll 4
        for (int i = 0; i < 32; i++) {
            float wv = sm[W1 + 4096 + i*128 + oc];
            u64 wp = pk2(wv, wv);
            const int base = SS + i*34 + rb;
            #pragma unroll
            for (int p = 0; p < 4; p++) {
                u64 tv = *(const u64*)&sm[base + 2*p];
                gacc[p] = fma2(wp, tv, gacc[p]);
            }
        }
        #pragma unroll
        for (int p = 0; p < 4; p++) {
            float lo, hi; upk(gacc[p], lo, hi);
            const int a = O2T + oc*34 + rb + 2*p;
            sm[a]   *= sigm(lo);
            sm[a+1] *= sigm(hi);
        }
    }
    __syncthreads();

    // ---------------- stage H: residual gate ----------------
    {
        const float bgv = __ldg(bg);
        #pragma unroll
        for (int r2 = 0; r2 < 2; r2++) {
            const int row = 2*w + r2;
            float p = 0.0f;
            #pragma unroll
            for (int k = 0; k < 4; k++) {
                const int cx = lane + 32*k;
                p += sm[W1 + 8192 + cx]       * sm[XT  + cx*34 + row];
                p += sm[W1 + 8192 + 128 + cx] * sm[O2T + cx*34 + row];
            }
            #pragma unroll
            for (int o = 16; o; o >>= 1) p += __shfl_xor_sync(0xffffffffu, p, o);
            if (lane == 0) sm[GG + row] = sigm(p + bgv);
        }
    }
    __syncthreads();

    // ---------------- stage I: out = g*o3 + (1-g)*x ----------------
    {
        float4* og4 = (float4*)out + rowBase*32;
        #pragma unroll
        for (int it = 0; it < 2; it++) {
            const int idx = t + 512*it;
            const int r = idx >> 5, c4 = idx & 31;
            const float g = sm[GG + r];
            float4 res;
            res.x = g*sm[O2T + (c4*4+0)*34 + r] + (1.0f-g)*sm[XT + (c4*4+0)*34 + r];
            res.y = g*sm[O2T + (c4*4+1)*34 + r] + (1.0f-g)*sm[XT + (c4*4+1)*34 + r];
            res.z = g*sm[O2T + (c4*4+2)*34 + r] + (1.0f-g)*sm[XT + (c4*4+2)*34 + r];
            res.w = g*sm[O2T + (c4*4+3)*34 + r] + (1.0f-g)*sm[XT + (c4*4+3)*34 + r];
            og4[idx] = res;
        }
    }
}

// =======================================================================
extern "C" void kernel_launch(void* const* d_in, const int* in_sizes, int n_in,
                              void* d_out, int out_size)
{
    const float* x    = (const float*)d_in[0];
    const float* nb   = (const float*)d_in[1];
    const float* Wq   = (const float*)d_in[2];
    const float* bq   = (const float*)d_in[3];
    const float* Wk   = (const float*)d_in[4];
    // d_in[5] = bk : constant over n => softmax-invariant, unused
    const float* Wv   = (const float*)d_in[6];
    const float* bv   = (const float*)d_in[7];
    const float* Wo   = (const float*)d_in[8];
    const float* bo   = (const float*)d_in[9];
    const float* Wse1 = (const float*)d_in[10];
    const float* Wse2 = (const float*)d_in[11];
    const float* Wg   = (const float*)d_in[12];
    const float* bg   = (const float*)d_in[13];
    float* out = (float*)d_out;

    cudaFuncSetAttribute(k_fused, cudaFuncAttributeMaxDynamicSharedMemorySize,
                         SMEM_FLOATS * 4);

    k_pre<<<64, 256>>>(Wq, bq, Wv, Wo, Wse1, Wse2);
    k_fused<<<2048, 512, SMEM_FLOATS * 4>>>(x, nb, Wk, bv, bo, Wg, bg, out);
}

// round 6
// speedup vs baseline: 1.5542x; 1.5542x over previous
#include <cuda_runtime.h>
#include <math.h>

typedef unsigned long long u64;

// ---------------- pretransposed weights (device scratch) ----------------
__device__ float g_WqT[16384];   // [c][j] = Wq[j][c] * 1/sqrt(32)
__device__ float g_WvT[16384];   // [c][j] = Wv[j][c]
__device__ float g_WoT[16384];   // [j2][oc] = Wo[oc][j2]
__device__ float g_Se1T[4096];   // [oc][i] = Wse1[i][oc]
__device__ float g_Se2T[4096];   // [i][oc] = Wse2[oc][i]
__device__ float g_bqs[128];     // bq * 1/sqrt(32)

#define SCALE 0.17677669529663687f

__global__ void k_pre(const float* __restrict__ Wq, const float* __restrict__ bq,
                      const float* __restrict__ Wv, const float* __restrict__ Wo,
                      const float* __restrict__ Wse1, const float* __restrict__ Wse2)
{
    int i = blockIdx.x * 256 + threadIdx.x;
    if (i < 16384) {
        int a = i >> 7, b = i & 127;          // i = a*128 + b
        g_WqT[i] = Wq[b*128 + a] * SCALE;     // WqT[c][j]
        g_WvT[i] = Wv[b*128 + a];
        g_WoT[i] = Wo[b*128 + a];             // WoT[j2][oc]
    }
    if (i < 4096) {
        int oc1 = i >> 5, i1 = i & 31;        // i = oc1*32 + i1
        g_Se1T[i] = Wse1[i1*128 + oc1];
        int i2 = i >> 7, oc2 = i & 127;       // i = i2*128 + oc2
        g_Se2T[i] = Wse2[oc2*32 + i2];
    }
    if (i < 128) g_bqs[i] = bq[i] * SCALE;
}

// ---------------- helpers ----------------
__device__ __forceinline__ u64 pk2(float lo, float hi) {
    u64 r; asm("mov.b64 %0, {%1, %2};" : "=l"(r) : "f"(lo), "f"(hi)); return r;
}
__device__ __forceinline__ void upk(u64 v, float& lo, float& hi) {
    asm("mov.b64 {%0, %1}, %2;" : "=f"(lo), "=f"(hi) : "l"(v));
}
__device__ __forceinline__ u64 fma2(u64 a, u64 b, u64 c) {
    u64 d; asm("fma.rn.f32x2 %0, %1, %2, %3;" : "=l"(d) : "l"(a), "l"(b), "l"(c)); return d;
}
__device__ __forceinline__ void cpa16(unsigned dst, const void* src) {
    asm volatile("cp.async.cg.shared.global [%0], [%1], 16;" :: "r"(dst), "l"(src));
}
__device__ __forceinline__ void cp_commit() { asm volatile("cp.async.commit_group;"); }
__device__ __forceinline__ void cp_waitall() { asm volatile("cp.async.wait_group 0;" ::: "memory"); }
__device__ __forceinline__ float sigm(float z) { return 1.0f / (1.0f + __expf(-z)); }

// ---------------- smem layout (floats) ----------------
#define W1   0        // 16384: WqT -> WvT -> [Se1T | Se2T | Wg]
#define W2   16384    // 16384: Wk (verbatim) -> WoT
#define CTX  32768    // 17408: qk[32][512] -> ctxT[512][34] ; o2T[128][34]@+0 ; oT[128][34]@+13056
#define OT   (CTX + 13056)
#define O2T  (CTX + 0)
#define XT   50176    // 4352: xT[128][34]
#define SS   54528    // 2560: scores [(row*20+n)*4 + h] -> T1[i][34]
#define GG   57088    // 32: gates
#define SMEM_FLOATS 57120   // 228480 bytes

__global__ void __launch_bounds__(512, 1) k_fused(
    const float* __restrict__ x,
    const float* __restrict__ nb,
    const float* __restrict__ Wk,
    const float* __restrict__ bv, const float* __restrict__ bo,
    const float* __restrict__ Wg, const float* __restrict__ bg,
    float* __restrict__ out)
{
    extern __shared__ float sm[];
    const int t = threadIdx.x;
    const int lane = t & 31;
    const int w = t >> 5;              // warp 0..15
    const long rowBase = (long)blockIdx.x * 32;
    unsigned sb = (unsigned)__cvta_generic_to_shared(sm);

    // ---------------- phase 0: cp.async WqT->W1, Wk->W2 ; build xT ----------------
    #pragma unroll
    for (int i = t; i < 4096; i += 512) cpa16(sb + W1*4 + i*16, g_WqT + i*4);
    #pragma unroll
    for (int i = t; i < 4096; i += 512) cpa16(sb + W2*4 + i*16, Wk + i*4);
    cp_commit();
    {
        const float4* xg = (const float4*)x + rowBase*32;
        #pragma unroll
        for (int it = 0; it < 2; it++) {
            int idx = t + 512*it;
            int r = idx >> 5, c4 = idx & 31;
            float4 v = xg[idx];
            sm[XT + (c4*4+0)*34 + r] = v.x;
            sm[XT + (c4*4+1)*34 + r] = v.y;
            sm[XT + (c4*4+2)*34 + r] = v.z;
            sm[XT + (c4*4+3)*34 + r] = v.w;
        }
    }
    cp_waitall();
    __syncthreads();

    // ---------------- stage A: q = s*(Wq x + bq), kept in registers ----------------
    const int jg = w & 3, rg = w >> 2;
    const int rb = rg * 8;
    u64 q2[4];
    {
        const int j = jg*32 + lane;
        float b = g_bqs[j];
        u64 bb = pk2(b, b);
        #pragma unroll
        for (int p = 0; p < 4; p++) q2[p] = bb;
        #pragma unroll 4
        for (int c = 0; c < 128; c++) {
            float wq = sm[W1 + c*128 + j];
            u64 wp = pk2(wq, wq);
            #pragma unroll
            for (int p = 0; p < 4; p++) {
                u64 xp = *(const u64*)&sm[XT + c*34 + rb + 2*p];
                q2[p] = fma2(wp, xp, q2[p]);
            }
        }
    }
    __syncwarp();

    // ---------------- stage B: qk = q^T Wk (head h = jg), q via shuffles ----------------
    {
        float qlo[4], qhi[4];
        #pragma unroll
        for (int p = 0; p < 4; p++) upk(q2[p], qlo[p], qhi[p]);
        u64 acc[4][4];
        #pragma unroll
        for (int k = 0; k < 4; k++)
            #pragma unroll
            for (int p = 0; p < 4; p++) acc[k][p] = 0ull;
        #pragma unroll 2
        for (int d = 0; d < 32; d++) {
            u64 qq[4];
            #pragma unroll
            for (int p = 0; p < 4; p++) {
                float a = __shfl_sync(0xffffffffu, qlo[p], d);
                float b = __shfl_sync(0xffffffffu, qhi[p], d);
                qq[p] = pk2(a, b);
            }
            const int jrow = W2 + (jg*32 + d)*128 + lane;
            #pragma unroll
            for (int k = 0; k < 4; k++) {
                float wk = sm[jrow + 32*k];
                u64 wp = pk2(wk, wk);
                #pragma unroll
                for (int p = 0; p < 4; p++) acc[k][p] = fma2(wp, qq[p], acc[k][p]);
            }
        }
        #pragma unroll
        for (int k = 0; k < 4; k++)
            #pragma unroll
            for (int p = 0; p < 4; p++) {
                float lo, hi; upk(acc[k][p], lo, hi);
                sm[CTX + (rb+2*p  )*512 + jg*128 + lane + 32*k] = lo;
                sm[CTX + (rb+2*p+1)*512 + jg*128 + lane + 32*k] = hi;
            }
    }
    __syncthreads();

    // prefetch WvT -> W1, WoT -> W2 (overlaps attention phase)
    #pragma unroll
    for (int i = t; i < 4096; i += 512) cpa16(sb + W1*4 + i*16, g_WvT + i*4);
    #pragma unroll
    for (int i = t; i < 4096; i += 512) cpa16(sb + W2*4 + i*16, g_WoT + i*4);
    cp_commit();

    // ---------------- stage C1: scores ----------------
    for (int idx = t; idx < 640; idx += 512) {
        const int row = idx / 20;
        const int n = idx - row*20;
        const float4* nbp = (const float4*)(nb + (((rowBase + row)*20 + n) << 7));
        float a0 = 0.f, a1 = 0.f, a2 = 0.f, a3 = 0.f;
        #pragma unroll 8
        for (int c4 = 0; c4 < 32; c4++) {
            float4 v = nbp[c4];
            float4 h0 = *(const float4*)&sm[CTX + row*512 +   0 + c4*4];
            float4 h1 = *(const float4*)&sm[CTX + row*512 + 128 + c4*4];
            float4 h2 = *(const float4*)&sm[CTX + row*512 + 256 + c4*4];
            float4 h3 = *(const float4*)&sm[CTX + row*512 + 384 + c4*4];
            a0 += h0.x*v.x + h0.y*v.y + h0.z*v.z + h0.w*v.w;
            a1 += h1.x*v.x + h1.y*v.y + h1.z*v.z + h1.w*v.w;
            a2 += h2.x*v.x + h2.y*v.y + h2.z*v.z + h2.w*v.w;
            a3 += h3.x*v.x + h3.y*v.y + h3.z*v.z + h3.w*v.w;
        }
        *(float4*)&sm[SS + idx*4] = make_float4(a0, a1, a2, a3);
    }
    __syncthreads();

    // ---------------- stage C2: softmax over n (128 threads) ----------------
    if (t < 128) {
        const int row = t >> 2, h = t & 3;
        const int base = SS + row*80 + h;
        float m = -1e30f;
        float s[20];
        #pragma unroll
        for (int n = 0; n < 20; n++) { s[n] = sm[base + n*4]; m = fmaxf(m, s[n]); }
        float tot = 0.f;
        #pragma unroll
        for (int n = 0; n < 20; n++) { s[n] = __expf(s[n] - m); tot += s[n]; }
        float inv = 1.0f / tot;
        #pragma unroll
        for (int n = 0; n < 20; n++) sm[base + n*4] = s[n] * inv;
    }
    __syncthreads();

    // ---------------- stage C3: ctxT[h*128+c][row] ----------------
    {
        const int cq = w & 3, rq = w >> 2;
        const int c = cq*32 + lane;
        u64 cacc[8][2];
        #pragma unroll
        for (int r = 0; r < 8; r++) { cacc[r][0] = 0ull; cacc[r][1] = 0ull; }
        #pragma unroll
        for (int r = 0; r < 8; r++) {
            const int row = rq*8 + r;
            const float* nbr = nb + ((rowBase + row)*20 << 7) + c;
            #pragma unroll 4
            for (int n = 0; n < 20; n++) {
                float v = __ldg(nbr + n*128);
                u64 vp = pk2(v, v);
                u64 a01 = *(const u64*)&sm[SS + row*80 + n*4];
                u64 a23 = *(const u64*)&sm[SS + row*80 + n*4 + 2];
                cacc[r][0] = fma2(a01, vp, cacc[r][0]);
                cacc[r][1] = fma2(a23, vp, cacc[r][1]);
            }
        }
        __syncthreads();   // qk fully consumed (C1) before ctxT overwrites region
        #pragma unroll
        for (int r = 0; r < 8; r++) {
            const int row = rq*8 + r;
            float v0, v1, v2, v3;
            upk(cacc[r][0], v0, v1);
            upk(cacc[r][1], v2, v3);
            sm[CTX + (0*128 + c)*34 + row] = v0;
            sm[CTX + (1*128 + c)*34 + row] = v1;
            sm[CTX + (2*128 + c)*34 + row] = v2;
            sm[CTX + (3*128 + c)*34 + row] = v3;
        }
    }
    cp_waitall();          // WvT / WoT landed
    __syncthreads();

    // ---------------- stage D: o = Wv ctx + bv ----------------
    u64 dacc[4];
    {
        const int h = jg;                     // reuse warp mapping (h, rg)
        const int j = h*32 + lane;
        float b = __ldg(&bv[j]);
        u64 bb = pk2(b, b);
        #pragma unroll
        for (int p = 0; p < 4; p++) dacc[p] = bb;
        #pragma unroll 2
        for (int c = 0; c < 128; c++) {
            float wv = sm[W1 + c*128 + j];
            u64 wp = pk2(wv, wv);
            const int base = CTX + (h*128 + c)*34 + rb;
            #pragma unroll
            for (int p = 0; p < 4; p++) {
                u64 cv = *(const u64*)&sm[base + 2*p];
                dacc[p] = fma2(wp, cv, dacc[p]);
            }
        }
    }
    __syncthreads();       // all ctxT reads done before oT overwrites tail of region
    {
        const int j2 = lane*4 + jg;           // permuted index d*4+h
        #pragma unroll
        for (int p = 0; p < 4; p++)
            *(u64*)&sm[OT + j2*34 + rb + 2*p] = dacc[p];
    }
    // prefetch SE weights -> W1 (Wv dead)
    #pragma unroll
    for (int i = t; i < 1024; i += 512) cpa16(sb + W1*4 + i*16, g_Se1T + i*4);
    #pragma unroll
    for (int i = t; i < 1024; i += 512) cpa16(sb + (W1+4096)*4 + i*16, g_Se2T + i*4);
    if (t < 64) cpa16(sb + (W1+8192)*4 + t*16, Wg + t*4);
    cp_commit();
    __syncthreads();       // oT visible

    // ---------------- stage E: o2 = WoT . o + bo ----------------
    {
        const int oc = jg*32 + lane;          // (og, rg) mapping
        float b = __ldg(&bo[oc]);
        u64 bb = pk2(b, b);
        u64 eacc[4];
        #pragma unroll
        for (int p = 0; p < 4; p++) eacc[p] = bb;
        #pragma unroll 2
        for (int j2 = 0; j2 < 128; j2++) {
            float wo = sm[W2 + j2*128 + oc];
            u64 wp = pk2(wo, wo);
            const int base = OT + j2*34 + rb;
            #pragma unroll
            for (int p = 0; p < 4; p++) {
                u64 ov = *(const u64*)&sm[base + 2*p];
                eacc[p] = fma2(wp, ov, eacc[p]);
            }
        }
        #pragma unroll
        for (int p = 0; p < 4; p++)           // o2T region disjoint from oT
            *(u64*)&sm[O2T + oc*34 + rb + 2*p] = eacc[p];
    }
    cp_waitall();          // SE weights landed
    __syncthreads();

    // ---------------- stage F: T1 = relu(Se1 . o2), row-pair per warp ----------------
    {
        u64 facc = 0ull;
        #pragma unroll 4
        for (int oc = 0; oc < 128; oc++) {
            float wv = sm[W1 + oc*32 + lane];
            u64 wp = pk2(wv, wv);
            u64 ov = *(const u64*)&sm[O2T + oc*34 + 2*w];
            facc = fma2(wp, ov, facc);
        }
        float lo, hi; upk(facc, lo, hi);
        lo = fmaxf(lo, 0.0f); hi = fmaxf(hi, 0.0f);
        *(u64*)&sm[SS + lane*34 + 2*w] = pk2(lo, hi);   // T1[i][rowpos]
    }
    __syncthreads();

    // ---------------- stage G: o2 *= sigmoid(Se2 . T1) ----------------
    {
        const int oc = jg*32 + lane;
        u64 gacc[4];
        #pragma unroll
        for (int p = 0; p < 4; p++) gacc[p] = 0ull;
        #pragma unroll 4
        for (int i = 0; i < 32; i++) {
            float wv = sm[W1 + 4096 + i*128 + oc];
            u64 wp = pk2(wv, wv);
            const int base = SS + i*34 + rb;
            #pragma unroll
            for (int p = 0; p < 4; p++) {
                u64 tv = *(const u64*)&sm[base + 2*p];
                gacc[p] = fma2(wp, tv, gacc[p]);
            }
        }
        #pragma unroll
        for (int p = 0; p < 4; p++) {
            float lo, hi; upk(gacc[p], lo, hi);
            const int a = O2T + oc*34 + rb + 2*p;
            sm[a]   *= sigm(lo);
            sm[a+1] *= sigm(hi);
        }
    }
    __syncthreads();

    // ---------------- stage H: residual gate ----------------
    {
        const float bgv = __ldg(bg);
        #pragma unroll
        for (int r2 = 0; r2 < 2; r2++) {
            const int row = 2*w + r2;
            float p = 0.0f;
            #pragma unroll
            for (int k = 0; k < 4; k++) {
                const int cx = lane + 32*k;
                p += sm[W1 + 8192 + cx]       * sm[XT  + cx*34 + row];
                p += sm[W1 + 8192 + 128 + cx] * sm[O2T + cx*34 + row];
            }
            #pragma unroll
            for (int o = 16; o; o >>= 1) p += __shfl_xor_sync(0xffffffffu, p, o);
            if (lane == 0) sm[GG + row] = sigm(p + bgv);
        }
    }
    __syncthreads();

    // ---------------- stage I: out = g*o3 + (1-g)*x ----------------
    {
        float4* og4 = (float4*)out + rowBase*32;
        #pragma unroll
        for (int it = 0; it < 2; it++) {
            const int idx = t + 512*it;
            const int r = idx >> 5, c4 = idx & 31;
            const float g = sm[GG + r];
            float4 res;
            res.x = g*sm[O2T + (c4*4+0)*34 + r] + (1.0f-g)*sm[XT + (c4*4+0)*34 + r];
            res.y = g*sm[O2T + (c4*4+1)*34 + r] + (1.0f-g)*sm[XT + (c4*4+1)*34 + r];
            res.z = g*sm[O2T + (c4*4+2)*34 + r] + (1.0f-g)*sm[XT + (c4*4+2)*34 + r];
            res.w = g*sm[O2T + (c4*4+3)*34 + r] + (1.0f-g)*sm[XT + (c4*4+3)*34 + r];
            og4[idx] = res;
        }
    }
}

// =======================================================================
extern "C" void kernel_launch(void* const* d_in, const int* in_sizes, int n_in,
                              void* d_out, int out_size)
{
    const float* x    = (const float*)d_in[0];
    const float* nb   = (const float*)d_in[1];
    const float* Wq   = (const float*)d_in[2];
    const float* bq   = (const float*)d_in[3];
    const float* Wk   = (const float*)d_in[4];
    // d_in[5] = bk : constant over n => softmax-invariant, unused
    const float* Wv   = (const float*)d_in[6];
    const float* bv   = (const float*)d_in[7];
    const float* Wo   = (const float*)d_in[8];
    const float* bo   = (const float*)d_in[9];
    const float* Wse1 = (const float*)d_in[10];
    const float* Wse2 = (const float*)d_in[11];
    const float* Wg   = (const float*)d_in[12];
    const float* bg   = (const float*)d_in[13];
    float* out = (float*)d_out;

    cudaFuncSetAttribute(k_fused, cudaFuncAttributeMaxDynamicSharedMemorySize,
                         SMEM_FLOATS * 4);

    k_pre<<<64, 256>>>(Wq, bq, Wv, Wo, Wse1, Wse2);
    k_fused<<<2048, 512, SMEM_FLOATS * 4>>>(x, nb, Wk, bv, bo, Wg, bg, out);
}

// round 7
// speedup vs baseline: 1.5770x; 1.0147x over previous
#include <cuda_runtime.h>
#include <math.h>

typedef unsigned long long u64;

// ---------------- pretransposed weights (device scratch) ----------------
__device__ float g_WqT[16384];   // [c][j] = Wq[j][c] * 1/sqrt(32)
__device__ float g_WvT[16384];   // [c][j] = Wv[j][c]
__device__ float g_WoP[16384];   // [j][oc] = Wo[oc][(j&31)*4 + (j>>5)]  (permute folded)
__device__ float g_Se1T[4096];   // [oc][i] = Wse1[i][oc]
__device__ float g_Se2T[4096];   // [i][oc] = Wse2[oc][i]
__device__ float g_bqs[128];     // bq * 1/sqrt(32)

#define SCALE 0.17677669529663687f

__global__ void k_pre(const float* __restrict__ Wq, const float* __restrict__ bq,
                      const float* __restrict__ Wv, const float* __restrict__ Wo,
                      const float* __restrict__ Wse1, const float* __restrict__ Wse2)
{
    int i = blockIdx.x * 256 + threadIdx.x;
    if (i < 16384) {
        int a = i >> 7, b = i & 127;
        g_WqT[i] = Wq[b*128 + a] * SCALE;      // WqT[c][j]
        g_WvT[i] = Wv[b*128 + a];              // WvT[c][j]
        int j = a, oc = b;
        g_WoP[i] = Wo[oc*128 + ((j & 31)*4 + (j >> 5))];
    }
    if (i < 4096) {
        int oc1 = i >> 5, i1 = i & 31;
        g_Se1T[i] = Wse1[i1*128 + oc1];
        int i2 = i >> 7, oc2 = i & 127;
        g_Se2T[i] = Wse2[oc2*32 + i2];
    }
    if (i < 128) g_bqs[i] = bq[i] * SCALE;
}

// ---------------- helpers ----------------
__device__ __forceinline__ u64 pk2(float lo, float hi) {
    u64 r; asm("mov.b64 %0, {%1, %2};" : "=l"(r) : "f"(lo), "f"(hi)); return r;
}
__device__ __forceinline__ void upk(u64 v, float& lo, float& hi) {
    asm("mov.b64 {%0, %1}, %2;" : "=f"(lo), "=f"(hi) : "l"(v));
}
__device__ __forceinline__ u64 fma2(u64 a, u64 b, u64 c) {
    u64 d; asm("fma.rn.f32x2 %0, %1, %2, %3;" : "=l"(d) : "l"(a), "l"(b), "l"(c)); return d;
}
__device__ __forceinline__ void cpa16(unsigned dst, const void* src) {
    asm volatile("cp.async.cg.shared.global [%0], [%1], 16;" :: "r"(dst), "l"(src));
}
__device__ __forceinline__ void cp_commit() { asm volatile("cp.async.commit_group;"); }
__device__ __forceinline__ void cp_waitall() { asm volatile("cp.async.wait_group 0;" ::: "memory"); }
__device__ __forceinline__ float sigm(float z) { return 1.0f / (1.0f + __expf(-z)); }

// ---------------- smem layout (floats), 32 rows/block ----------------
#define W1   0        // 16384: WqT -> WvT -> [Se1T | Se2T@+4096 | Wg@+8192]
#define W2   16384    // 16384: Wk (natural [j][c]) -> WoP
#define CTX  32768    // 17408: qT[128][34]@+0 -> qk[32][512] -> ctxT[(h*128+c)][34]
#define OT   (CTX + 13056)   // oT[j][34] (over ctxT tail)
#define O2T  (CTX + 0)       // o2T[oc][34] (over ctxT head)
#define XT   50176    // 4352: xT[128][34]
#define SS   54528    // 2560: scores[row][n][4h] -> T1T[i][34]
#define GG   57088    // 32 gates
#define SMEM_FLOATS 57120    // 228480 B

__global__ void __launch_bounds__(512, 1) k_fused(
    const float* __restrict__ x,
    const float* __restrict__ nb,
    const float* __restrict__ Wk,
    const float* __restrict__ bv, const float* __restrict__ bo,
    const float* __restrict__ Wg, const float* __restrict__ bg,
    float* __restrict__ out)
{
    extern __shared__ float sm[];
    const int t = threadIdx.x;
    const int lane = t & 31;
    const int w = t >> 5;               // warp 0..15
    const int jl = lane & 7;            // j-lane (8)
    const int rg = lane >> 3;           // row-group (4)
    const int qg = w & 3;               // quadrant (j/oc/head)
    const int rq = w >> 2;              // row-quarter
    const int jbase = qg*32 + jl*4;     // j/oc quad base
    const int rpos = rq*8 + rg*2;       // row pair position
    const long rowBase = (long)blockIdx.x * 32;
    unsigned sb = (unsigned)__cvta_generic_to_shared(sm);

    // ============ phase 0: WqT->W1, Wk->W2 (cp.async); build xT ============
    #pragma unroll
    for (int i = t; i < 4096; i += 512) cpa16(sb + W1*4 + i*16, g_WqT + i*4);
    #pragma unroll
    for (int i = t; i < 4096; i += 512) cpa16(sb + W2*4 + i*16, Wk + i*4);
    cp_commit();
    {
        const float4* xg = (const float4*)x + rowBase*32;
        #pragma unroll
        for (int it = 0; it < 2; it++) {
            int idx = t + 512*it;
            int r = idx >> 5, c4 = idx & 31;
            float4 v = xg[idx];
            sm[XT + (c4*4+0)*34 + r] = v.x;
            sm[XT + (c4*4+1)*34 + r] = v.y;
            sm[XT + (c4*4+2)*34 + r] = v.z;
            sm[XT + (c4*4+3)*34 + r] = v.w;
        }
    }
    cp_waitall();
    __syncthreads();

    // ============ stage A: q = s*(Wq x + bq) -> qT[j][34] ============
    {
        u64 a0, a1, a2, a3;
        { float b0 = g_bqs[jbase], b1 = g_bqs[jbase+1],
                b2 = g_bqs[jbase+2], b3 = g_bqs[jbase+3];
          a0 = pk2(b0,b0); a1 = pk2(b1,b1); a2 = pk2(b2,b2); a3 = pk2(b3,b3); }
        #pragma unroll 4
        for (int c = 0; c < 128; c++) {
            float4 wv = *(const float4*)&sm[W1 + c*128 + jbase];
            u64 xp = *(const u64*)&sm[XT + c*34 + rpos];
            a0 = fma2(pk2(wv.x,wv.x), xp, a0);
            a1 = fma2(pk2(wv.y,wv.y), xp, a1);
            a2 = fma2(pk2(wv.z,wv.z), xp, a2);
            a3 = fma2(pk2(wv.w,wv.w), xp, a3);
        }
        *(u64*)&sm[CTX + (jbase+0)*34 + rpos] = a0;
        *(u64*)&sm[CTX + (jbase+1)*34 + rpos] = a1;
        *(u64*)&sm[CTX + (jbase+2)*34 + rpos] = a2;
        *(u64*)&sm[CTX + (jbase+3)*34 + rpos] = a3;
    }
    __syncthreads();
    // W1 free -> prefetch WvT
    #pragma unroll
    for (int i = t; i < 4096; i += 512) cpa16(sb + W1*4 + i*16, g_WvT + i*4);
    cp_commit();

    // ============ stage B: qk[row][h*128+c] = sum_d q[row][h*32+d]*Wk[h*32+d][c] ============
    {
        u64 acc[4][4];                        // [cc][cq]
        #pragma unroll
        for (int cc = 0; cc < 4; cc++)
            #pragma unroll
            for (int q = 0; q < 4; q++) acc[cc][q] = 0ull;
        #pragma unroll 4
        for (int d = 0; d < 32; d++) {
            const int j = qg*32 + d;          // head = qg
            u64 qp = *(const u64*)&sm[CTX + j*34 + rpos];
            #pragma unroll
            for (int cc = 0; cc < 4; cc++) {
                float4 wv = *(const float4*)&sm[W2 + j*128 + cc*32 + jl*4];
                acc[cc][0] = fma2(pk2(wv.x,wv.x), qp, acc[cc][0]);
                acc[cc][1] = fma2(pk2(wv.y,wv.y), qp, acc[cc][1]);
                acc[cc][2] = fma2(pk2(wv.z,wv.z), qp, acc[cc][2]);
                acc[cc][3] = fma2(pk2(wv.w,wv.w), qp, acc[cc][3]);
            }
        }
        __syncthreads();      // all qT reads drained before qk overwrites region
        #pragma unroll
        for (int rr = 0; rr < 2; rr++) {
            #pragma unroll
            for (int cc = 0; cc < 4; cc++) {
                float4 o; float lo, hi;
                upk(acc[cc][0], lo, hi); o.x = rr ? hi : lo;
                upk(acc[cc][1], lo, hi); o.y = rr ? hi : lo;
                upk(acc[cc][2], lo, hi); o.z = rr ? hi : lo;
                upk(acc[cc][3], lo, hi); o.w = rr ? hi : lo;
                *(float4*)&sm[CTX + (rpos+rr)*512 + qg*128 + cc*32 + jl*4] = o;
            }
        }
    }
    __syncthreads();
    // W2 free -> prefetch WoP
    #pragma unroll
    for (int i = t; i < 4096; i += 512) cpa16(sb + W2*4 + i*16, g_WoP + i*4);
    cp_commit();

    // ============ stage C1: scores ============
    for (int idx = t; idx < 640; idx += 512) {
        const int row = idx / 20;
        const int n = idx - row*20;
        const float4* nbp = (const float4*)(nb + (((rowBase + row)*20 + n) << 7));
        float a0 = 0.f, a1 = 0.f, a2 = 0.f, a3 = 0.f;
        #pragma unroll 8
        for (int c4 = 0; c4 < 32; c4++) {
            float4 v = nbp[c4];
            float4 h0 = *(const float4*)&sm[CTX + row*512 +   0 + c4*4];
            float4 h1 = *(const float4*)&sm[CTX + row*512 + 128 + c4*4];
            float4 h2 = *(const float4*)&sm[CTX + row*512 + 256 + c4*4];
            float4 h3 = *(const float4*)&sm[CTX + row*512 + 384 + c4*4];
            a0 += h0.x*v.x + h0.y*v.y + h0.z*v.z + h0.w*v.w;
            a1 += h1.x*v.x + h1.y*v.y + h1.z*v.z + h1.w*v.w;
            a2 += h2.x*v.x + h2.y*v.y + h2.z*v.z + h2.w*v.w;
            a3 += h3.x*v.x + h3.y*v.y + h3.z*v.z + h3.w*v.w;
        }
        *(float4*)&sm[SS + idx*4] = make_float4(a0, a1, a2, a3);
    }
    __syncthreads();

    // ============ stage C2: softmax over n ============
    if (t < 128) {
        const int row = t >> 2, h = t & 3;
        const int base = SS + row*80 + h;
        float m = -1e30f;
        float s[20];
        #pragma unroll
        for (int n = 0; n < 20; n++) { s[n] = sm[base + n*4]; m = fmaxf(m, s[n]); }
        float tot = 0.f;
        #pragma unroll
        for (int n = 0; n < 20; n++) { s[n] = __expf(s[n] - m); tot += s[n]; }
        float inv = 1.0f / tot;
        #pragma unroll
        for (int n = 0; n < 20; n++) sm[base + n*4] = s[n] * inv;
    }
    __syncthreads();

    // ============ stage C3: ctxT[(h*128+c)][row] ============
    {
        const int cq = w & 3, rq3 = w >> 2;
        const int c = cq*32 + lane;
        u64 cacc[8][2];
        #pragma unroll
        for (int r = 0; r < 8; r++) { cacc[r][0] = 0ull; cacc[r][1] = 0ull; }
        #pragma unroll
        for (int r = 0; r < 8; r++) {
            const int row = rq3*8 + r;
            const float* nbr = nb + ((rowBase + row)*20 << 7) + c;
            #pragma unroll 4
            for (int n = 0; n < 20; n++) {
                float v = __ldg(nbr + n*128);
                u64 vp = pk2(v, v);
                float4 at = *(const float4*)&sm[SS + row*80 + n*4];
                cacc[r][0] = fma2(pk2(at.x, at.y), vp, cacc[r][0]);
                cacc[r][1] = fma2(pk2(at.z, at.w), vp, cacc[r][1]);
            }
        }
        __syncthreads();   // qk fully consumed before ctxT overwrites region
        #pragma unroll
        for (int r = 0; r < 8; r++) {
            const int row = rq3*8 + r;
            float v0, v1, v2, v3;
            upk(cacc[r][0], v0, v1);
            upk(cacc[r][1], v2, v3);
            sm[CTX + (0*128 + c)*34 + row] = v0;
            sm[CTX + (1*128 + c)*34 + row] = v1;
            sm[CTX + (2*128 + c)*34 + row] = v2;
            sm[CTX + (3*128 + c)*34 + row] = v3;
        }
    }
    cp_waitall();          // WvT / WoP landed
    __syncthreads();

    // ============ stage D: o = Wv ctx + bv -> oT[j][34] (head = qg) ============
    {
        u64 a0, a1, a2, a3;
        { float b0 = __ldg(&bv[jbase]),   b1 = __ldg(&bv[jbase+1]),
                b2 = __ldg(&bv[jbase+2]), b3 = __ldg(&bv[jbase+3]);
          a0 = pk2(b0,b0); a1 = pk2(b1,b1); a2 = pk2(b2,b2); a3 = pk2(b3,b3); }
        #pragma unroll 4
        for (int c = 0; c < 128; c++) {
            float4 wv = *(const float4*)&sm[W1 + c*128 + jbase];
            u64 cp = *(const u64*)&sm[CTX + (qg*128 + c)*34 + rpos];
            a0 = fma2(pk2(wv.x,wv.x), cp, a0);
            a1 = fma2(pk2(wv.y,wv.y), cp, a1);
            a2 = fma2(pk2(wv.z,wv.z), cp, a2);
            a3 = fma2(pk2(wv.w,wv.w), cp, a3);
        }
        __syncthreads();   // all ctxT reads done before oT overwrites tail
        *(u64*)&sm[OT + (jbase+0)*34 + rpos] = a0;
        *(u64*)&sm[OT + (jbase+1)*34 + rpos] = a1;
        *(u64*)&sm[OT + (jbase+2)*34 + rpos] = a2;
        *(u64*)&sm[OT + (jbase+3)*34 + rpos] = a3;
    }
    // W1 free -> prefetch SE weights
    #pragma unroll
    for (int i = t; i < 1024; i += 512) cpa16(sb + W1*4 + i*16, g_Se1T + i*4);
    #pragma unroll
    for (int i = t; i < 1024; i += 512) cpa16(sb + (W1+4096)*4 + i*16, g_Se2T + i*4);
    if (t < 64) cpa16(sb + (W1+8192)*4 + t*16, Wg + t*4);
    cp_commit();
    __syncthreads();       // oT visible

    // ============ stage E: o2 = WoP . o + bo -> o2T[oc][34] ============
    {
        u64 a0, a1, a2, a3;
        { float b0 = __ldg(&bo[jbase]),   b1 = __ldg(&bo[jbase+1]),
                b2 = __ldg(&bo[jbase+2]), b3 = __ldg(&bo[jbase+3]);
          a0 = pk2(b0,b0); a1 = pk2(b1,b1); a2 = pk2(b2,b2); a3 = pk2(b3,b3); }
        #pragma unroll 4
        for (int j = 0; j < 128; j++) {
            float4 wv = *(const float4*)&sm[W2 + j*128 + jbase];
            u64 op = *(const u64*)&sm[OT + j*34 + rpos];
            a0 = fma2(pk2(wv.x,wv.x), op, a0);
            a1 = fma2(pk2(wv.y,wv.y), op, a1);
            a2 = fma2(pk2(wv.z,wv.z), op, a2);
            a3 = fma2(pk2(wv.w,wv.w), op, a3);
        }
        // o2T region (ctxT head) disjoint from oT (tail): no hazard
        *(u64*)&sm[O2T + (jbase+0)*34 + rpos] = a0;
        *(u64*)&sm[O2T + (jbase+1)*34 + rpos] = a1;
        *(u64*)&sm[O2T + (jbase+2)*34 + rpos] = a2;
        *(u64*)&sm[O2T + (jbase+3)*34 + rpos] = a3;
    }
    cp_waitall();          // SE weights landed
    __syncthreads();

    // ============ stage F: T1 = relu(Se1 . o2) -> T1T[i][34]  (4 warps) ============
    if (w < 4) {
        const int fr = w*8 + rg*2;             // row pair
        u64 a0 = 0ull, a1 = 0ull, a2 = 0ull, a3 = 0ull;
        #pragma unroll 4
        for (int oc = 0; oc < 128; oc++) {
            float4 wv = *(const float4*)&sm[W1 + oc*32 + jl*4];
            u64 op = *(const u64*)&sm[O2T + oc*34 + fr];
            a0 = fma2(pk2(wv.x,wv.x), op, a0);
            a1 = fma2(pk2(wv.y,wv.y), op, a1);
            a2 = fma2(pk2(wv.z,wv.z), op, a2);
            a3 = fma2(pk2(wv.w,wv.w), op, a3);
        }
        float lo, hi;
        upk(a0, lo, hi); *(u64*)&sm[SS + (jl*4+0)*34 + fr] = pk2(fmaxf(lo,0.f), fmaxf(hi,0.f));
        upk(a1, lo, hi); *(u64*)&sm[SS + (jl*4+1)*34 + fr] = pk2(fmaxf(lo,0.f), fmaxf(hi,0.f));
        upk(a2, lo, hi); *(u64*)&sm[SS + (jl*4+2)*34 + fr] = pk2(fmaxf(lo,0.f), fmaxf(hi,0.f));
        upk(a3, lo, hi); *(u64*)&sm[SS + (jl*4+3)*34 + fr] = pk2(fmaxf(lo,0.f), fmaxf(hi,0.f));
    }
    __syncthreads();

    // ============ stage G: o2 *= sigmoid(Se2 . T1) ============
    {
        u64 a0 = 0ull, a1 = 0ull, a2 = 0ull, a3 = 0ull;
        #pragma unroll 4
        for (int i = 0; i < 32; i++) {
            float4 wv = *(const float4*)&sm[W1 + 4096 + i*128 + jbase];
            u64 tp = *(const u64*)&sm[SS + i*34 + rpos];
            a0 = fma2(pk2(wv.x,wv.x), tp, a0);
            a1 = fma2(pk2(wv.y,wv.y), tp, a1);
            a2 = fma2(pk2(wv.z,wv.z), tp, a2);
            a3 = fma2(pk2(wv.w,wv.w), tp, a3);
        }
        u64 se[4] = {a0, a1, a2, a3};
        #pragma unroll
        for (int q = 0; q < 4; q++) {
            float lo, hi; upk(se[q], lo, hi);
            const int a = O2T + (jbase+q)*34 + rpos;
            sm[a]   *= sigm(lo);
            sm[a+1] *= sigm(hi);
        }
    }
    __syncthreads();

    // ============ stage H: residual gate ============
    {
        const float bgv = __ldg(bg);
        #pragma unroll
        for (int r2 = 0; r2 < 2; r2++) {
            const int row = 2*w + r2;
            float p = 0.0f;
            #pragma unroll
            for (int k = 0; k < 4; k++) {
                const int cx = lane + 32*k;
                p += sm[W1 + 8192 + cx]       * sm[XT  + cx*34 + row];
                p += sm[W1 + 8192 + 128 + cx] * sm[O2T + cx*34 + row];
            }
            #pragma unroll
            for (int o = 16; o; o >>= 1) p += __shfl_xor_sync(0xffffffffu, p, o);
            if (lane == 0) sm[GG + row] = sigm(p + bgv);
        }
    }
    __syncthreads();

    // ============ stage I: out = g*o3 + (1-g)*x ============
    {
        float4* og4 = (float4*)out + rowBase*32;
        #pragma unroll
        for (int it = 0; it < 2; it++) {
            const int idx = t + 512*it;
            const int r = idx >> 5, c4 = idx & 31;
            const float g = sm[GG + r];
            float4 res;
            res.x = g*sm[O2T + (c4*4+0)*34 + r] + (1.0f-g)*sm[XT + (c4*4+0)*34 + r];
            res.y = g*sm[O2T + (c4*4+1)*34 + r] + (1.0f-g)*sm[XT + (c4*4+1)*34 + r];
            res.z = g*sm[O2T + (c4*4+2)*34 + r] + (1.0f-g)*sm[XT + (c4*4+2)*34 + r];
            res.w = g*sm[O2T + (c4*4+3)*34 + r] + (1.0f-g)*sm[XT + (c4*4+3)*34 + r];
            og4[idx] = res;
        }
    }
}

// =======================================================================
extern "C" void kernel_launch(void* const* d_in, const int* in_sizes, int n_in,
                              void* d_out, int out_size)
{
    const float* x    = (const float*)d_in[0];
    const float* nb   = (const float*)d_in[1];
    const float* Wq   = (const float*)d_in[2];
    const float* bq   = (const float*)d_in[3];
    const float* Wk   = (const float*)d_in[4];
    // d_in[5] = bk : constant over n => softmax-invariant, unused
    const float* Wv   = (const float*)d_in[6];
    const float* bv   = (const float*)d_in[7];
    const float* Wo   = (const float*)d_in[8];
    const float* bo   = (const float*)d_in[9];
    const float* Wse1 = (const float*)d_in[10];
    const float* Wse2 = (const float*)d_in[11];
    const float* Wg   = (const float*)d_in[12];
    const float* bg   = (const float*)d_in[13];
    float* out = (float*)d_out;

    cudaFuncSetAttribute(k_fused, cudaFuncAttributeMaxDynamicSharedMemorySize,
                         SMEM_FLOATS * 4);

    k_pre<<<64, 256>>>(Wq, bq, Wv, Wo, Wse1, Wse2);
    k_fused<<<2048, 512, SMEM_FLOATS * 4>>>(x, nb, Wk, bv, bo, Wg, bg, out);
}